// round 5
// baseline (speedup 1.0000x reference)
#include <cuda_runtime.h>
#include <cuda_bf16.h>
#include <math.h>

// Problem constants
#define S_LEN 2048
#define D_MODEL 2048
#define HEADS 32
#define HEAD_DIM 64
#define NKV 8
#define D_Q 2048
#define D_KV 512
#define D_QKV 3072   // q | k | v concatenated

// Scratch (__device__ globals; allocation-free rule)
__device__ float g_w[D_MODEL * D_QKV];    // concatenated Wq|Wk|Wv   (25 MB)
__device__ float g_qkv[S_LEN * D_QKV];    // fused qkv activations   (25 MB)
__device__ float g_ao[S_LEN * D_Q];       // attention output        (16 MB)

typedef unsigned long long u64;

// ---- packed fp32x2 helpers (sm_103a FFMA2: 2x fp32 FMA throughput) ----
__device__ __forceinline__ void fma2(u64& d, u64 a, u64 b) {
    asm("fma.rn.f32x2 %0, %1, %2, %0;" : "+l"(d) : "l"(a), "l"(b));
}
__device__ __forceinline__ u64 pack2(float x, float y) {
    u64 r; asm("mov.b64 %0, {%1, %2};" : "=l"(r) : "f"(x), "f"(y)); return r;
}
__device__ __forceinline__ float2 unpack2(u64 v) {
    float2 r; asm("mov.b64 {%0, %1}, %2;" : "=f"(r.x), "=f"(r.y) : "l"(v)); return r;
}
__device__ __forceinline__ void mul2(u64& d, u64 a) {
    asm("mul.rn.f32x2 %0, %0, %1;" : "+l"(d) : "l"(a));
}

// ---------------------------------------------------------------------------
// Concatenate Wq|Wk|Wv into g_w [D_MODEL][D_QKV]
// ---------------------------------------------------------------------------
__global__ __launch_bounds__(256) void concat_w_kernel(
    const float* __restrict__ Wq, const float* __restrict__ Wk,
    const float* __restrict__ Wv, float* __restrict__ W)
{
    int idx = blockIdx.x * 256 + threadIdx.x;       // float4 index
    int n = (idx % (D_QKV / 4)) * 4;
    int k = idx / (D_QKV / 4);
    float4 v;
    if (n < D_Q)              v = *(const float4*)(Wq + (size_t)k * D_Q  + n);
    else if (n < D_Q + D_KV)  v = *(const float4*)(Wk + (size_t)k * D_KV + (n - D_Q));
    else                      v = *(const float4*)(Wv + (size_t)k * D_KV + (n - D_Q - D_KV));
    *(float4*)(W + (size_t)k * D_QKV + n) = v;
}

// ---------------------------------------------------------------------------
// SGEMM 128x128x16, 256 threads, 8x8 per thread, FFMA2 (pairs over N).
// C[M,N] = A[M,K] @ B[K,N] (+bias). M%128==0, N%128==0, K%16==0.
// ---------------------------------------------------------------------------
__global__ __launch_bounds__(256, 2) void sgemm128(
    const float* __restrict__ A, const float* __restrict__ B,
    float* __restrict__ C, const float* __restrict__ bias,
    int M, int N, int K)
{
    __shared__ float As[128][20];    // natural [m][k], stride 20 (16B-aligned rows)
    __shared__ float Bs[16][128];    // natural [k][n]

    const int tid = threadIdx.x;
    const int tx = tid & 15;         // -> 8 cols (4 f32x2 pairs)
    const int ty = tid >> 4;         // -> 8 rows
    const int m0 = blockIdx.y * 128;
    const int n0 = blockIdx.x * 128;

    const int la_r = tid >> 2;              // 0..63 (+64)
    const int la_c = (tid & 3) * 4;
    const int lb_r = tid >> 5;              // 0..7 (+8)
    const int lb_c = (tid & 31) * 4;

    u64 acc[8][4];
    #pragma unroll
    for (int i = 0; i < 8; i++)
        #pragma unroll
        for (int j = 0; j < 4; j++) acc[i][j] = 0ull;

    const float* Arow0 = A + (size_t)(m0 + la_r) * K + la_c;
    const float* Arow1 = A + (size_t)(m0 + la_r + 64) * K + la_c;
    const float* Brow0 = B + (size_t)lb_r * N + n0 + lb_c;
    const float* Brow1 = B + (size_t)(lb_r + 8) * N + n0 + lb_c;

    for (int k0 = 0; k0 < K; k0 += 16) {
        float4 a0 = *(const float4*)(Arow0 + k0);
        float4 a1 = *(const float4*)(Arow1 + k0);
        float4 b0 = *(const float4*)(Brow0 + (size_t)k0 * N);
        float4 b1 = *(const float4*)(Brow1 + (size_t)k0 * N);
        *(float4*)&As[la_r][la_c]      = a0;
        *(float4*)&As[la_r + 64][la_c] = a1;
        *(float4*)&Bs[lb_r][lb_c]      = b0;
        *(float4*)&Bs[lb_r + 8][lb_c]  = b1;
        __syncthreads();

        #pragma unroll
        for (int kk = 0; kk < 16; kk++) {
            u64 bb[4];
            const u64* bp = (const u64*)&Bs[kk][tx * 8];
            bb[0] = bp[0]; bb[1] = bp[1]; bb[2] = bp[2]; bb[3] = bp[3];
            #pragma unroll
            for (int i = 0; i < 8; i++) {
                float a = As[ty * 8 + i][kk];
                u64 aa = pack2(a, a);
                #pragma unroll
                for (int j = 0; j < 4; j++) fma2(acc[i][j], aa, bb[j]);
            }
        }
        __syncthreads();
    }

    #pragma unroll
    for (int i = 0; i < 8; i++) {
        int m = m0 + ty * 8 + i;
        #pragma unroll
        for (int j = 0; j < 4; j++) {
            float2 v = unpack2(acc[i][j]);
            int n = n0 + tx * 8 + j * 2;
            if (bias) { v.x += bias[n]; v.y += bias[n + 1]; }
            *(float2*)&C[(size_t)m * N + n] = v;
        }
    }
}

// ---------------------------------------------------------------------------
// RMSNorm + RoPE, in place, 4 heads per 256-thread block.
// data points at the head-0 column of its tensor inside g_qkv (stride D_QKV).
// ---------------------------------------------------------------------------
__global__ __launch_bounds__(256) void norm_rope4(
    float* __restrict__ data, const float* __restrict__ scale,
    const float* __restrict__ sinp, const float* __restrict__ cosp)
{
    const int s   = blockIdx.x;
    const int sub = threadIdx.x >> 6;              // 0..3 (head within block)
    const int h   = blockIdx.y * 4 + sub;
    const int d   = threadIdx.x & 63;
    float* p = data + (size_t)s * D_QKV + h * HEAD_DIM + d;

    float v = *p;
    float sq = v * v;
    #pragma unroll
    for (int o = 16; o; o >>= 1) sq += __shfl_xor_sync(0xffffffffu, sq, o);
    __shared__ float ws[8];
    if ((threadIdx.x & 31) == 0) ws[threadIdx.x >> 5] = sq;
    __syncthreads();
    const float total = ws[sub * 2] + ws[sub * 2 + 1];
    const float r = rsqrtf(total * (1.0f / 64.0f) + 1e-6f);

    const float xn = v * r * scale[d];
    __shared__ float sm[4][64];
    sm[sub][d] = xn;
    __syncthreads();
    const float rot = (d < 32) ? -sm[sub][d + 32] : sm[sub][d - 32];
    *p = xn * cosp[s * HEAD_DIM + d] + rot * sinp[s * HEAD_DIM + d];
}

// ---------------------------------------------------------------------------
// Flash attention: block = (64-query tile, head). 256 threads, 4x4 microtile.
// Two inner GEMMs use FFMA2 paired over the contraction dim; K/V tiles are
// XOR-swizzled in smem for conflict-free column-pair reads.
// ---------------------------------------------------------------------------
extern __shared__ float s_attn[];   // Qs[64][68] | Ps[64][68] | Ks[64][64] | Vt[64][64]
#define ATTN_SMEM ((64*68 + 64*68 + 64*64 + 64*64) * 4)

__global__ __launch_bounds__(256, 2) void attn_flash(
    const float* __restrict__ qkv, float* __restrict__ out)
{
    float* Qs = s_attn;              // [q][d], stride 68
    float* Ps = Qs + 64 * 68;        // [q][k], stride 68
    float* Ks = Ps + 64 * 68;        // [k][d^sw], stride 64
    float* Vt = Ks + 64 * 64;        // [d][k^sw], stride 64

    const int t   = blockIdx.x;      // query tile
    const int h   = blockIdx.y;
    const int g   = h >> 2;          // kv head
    const int tid = threadIdx.x;
    const int tx  = tid & 15;
    const int ty  = tid >> 4;
    const int q0  = t * 64;

    // Load Q tile (rows q0..q0+63, head h)
    {
        int r = tid >> 2;
        int c = (tid & 3) * 16;
        const float* src = qkv + (size_t)(q0 + r) * D_QKV + h * HEAD_DIM + c;
        #pragma unroll
        for (int u = 0; u < 4; u++)
            *(float4*)&Qs[r * 68 + c + u * 4] = *(const float4*)(src + u * 4);
    }

    float mrow[4], lrow[4];
    #pragma unroll
    for (int i = 0; i < 4; i++) { mrow[i] = -1e30f; lrow[i] = 0.0f; }
    u64 accO[4][4];
    #pragma unroll
    for (int i = 0; i < 4; i++)
        #pragma unroll
        for (int j = 0; j < 4; j++) accO[i][j] = 0ull;

    const int colb = tx * 4;

    for (int jt = 0; jt <= t; jt++) {
        const int j0 = jt * 64;
        __syncthreads();   // previous O-GEMM / Q load done before Ks/Vt overwrite

        // Load K tile -> Ks[r][d ^ ((r&7)<<3)], V tile -> Vt[d][r ^ ((d&7)<<3)]
        {
            int r = tid >> 2;
            int cbase = (tid & 3) * 16;
            const float* ksrc = qkv + (size_t)(j0 + r) * D_QKV + D_Q + g * HEAD_DIM + cbase;
            const float* vsrc = ksrc + D_KV;
            int sw = (r & 7) << 3;
            #pragma unroll
            for (int u = 0; u < 4; u++) {
                float4 kv4 = *(const float4*)(ksrc + u * 4);
                *(float4*)&Ks[r * 64 + ((cbase + u * 4) ^ sw)] = kv4;
                float4 vv4 = *(const float4*)(vsrc + u * 4);
                int d = cbase + u * 4;
                Vt[(d + 0) * 64 + (r ^ (((d + 0) & 7) << 3))] = vv4.x;
                Vt[(d + 1) * 64 + (r ^ (((d + 1) & 7) << 3))] = vv4.y;
                Vt[(d + 2) * 64 + (r ^ (((d + 2) & 7) << 3))] = vv4.z;
                Vt[(d + 3) * 64 + (r ^ (((d + 3) & 7) << 3))] = vv4.w;
            }
        }
        __syncthreads();

        // S = Q @ K^T (pairs over d)
        u64 accS[4][4];
        #pragma unroll
        for (int i = 0; i < 4; i++)
            #pragma unroll
            for (int j = 0; j < 4; j++) accS[i][j] = 0ull;
        #pragma unroll 8
        for (int d0 = 0; d0 < 64; d0 += 2) {
            u64 ra[4], rb[4];
            #pragma unroll
            for (int i = 0; i < 4; i++) ra[i] = *(const u64*)&Qs[(ty * 4 + i) * 68 + d0];
            #pragma unroll
            for (int j = 0; j < 4; j++) {
                int r = colb + j;
                rb[j] = *(const u64*)&Ks[r * 64 + (d0 ^ ((r & 7) << 3))];
            }
            #pragma unroll
            for (int i = 0; i < 4; i++)
                #pragma unroll
                for (int j = 0; j < 4; j++) fma2(accS[i][j], ra[i], rb[j]);
        }
        float Sv[4][4];
        #pragma unroll
        for (int i = 0; i < 4; i++)
            #pragma unroll
            for (int j = 0; j < 4; j++) {
                float2 p = unpack2(accS[i][j]);
                Sv[i][j] = (p.x + p.y) * 0.125f;    // 1/sqrt(64)
            }

        if (jt == t) {   // causal mask within the diagonal tile
            #pragma unroll
            for (int i = 0; i < 4; i++) {
                int qr = ty * 4 + i;
                #pragma unroll
                for (int j = 0; j < 4; j++)
                    if (colb + j > qr) Sv[i][j] = -1e30f;
            }
        }

        // online softmax (row groups = 16 lanes sharing ty)
        float corr[4];
        #pragma unroll
        for (int i = 0; i < 4; i++) {
            float mx = fmaxf(fmaxf(Sv[i][0], Sv[i][1]), fmaxf(Sv[i][2], Sv[i][3]));
            #pragma unroll
            for (int o = 8; o; o >>= 1) mx = fmaxf(mx, __shfl_xor_sync(0xffffffffu, mx, o));
            float mnew = fmaxf(mrow[i], mx);
            corr[i] = __expf(mrow[i] - mnew);
            mrow[i] = mnew;
            float rs = 0.0f;
            #pragma unroll
            for (int j = 0; j < 4; j++) {
                float p = __expf(Sv[i][j] - mnew);
                Sv[i][j] = p; rs += p;
            }
            #pragma unroll
            for (int o = 8; o; o >>= 1) rs += __shfl_xor_sync(0xffffffffu, rs, o);
            lrow[i] = lrow[i] * corr[i] + rs;
        }
        #pragma unroll
        for (int i = 0; i < 4; i++) {
            u64 cc = pack2(corr[i], corr[i]);
            #pragma unroll
            for (int j = 0; j < 4; j++) mul2(accO[i][j], cc);
        }

        // store P tile
        #pragma unroll
        for (int i = 0; i < 4; i++)
            *(float4*)&Ps[(ty * 4 + i) * 68 + tx * 4] =
                make_float4(Sv[i][0], Sv[i][1], Sv[i][2], Sv[i][3]);
        __syncthreads();

        // O += P @ V (pairs over k)
        #pragma unroll 8
        for (int k0 = 0; k0 < 64; k0 += 2) {
            u64 ra[4], rb[4];
            #pragma unroll
            for (int i = 0; i < 4; i++) ra[i] = *(const u64*)&Ps[(ty * 4 + i) * 68 + k0];
            #pragma unroll
            for (int j = 0; j < 4; j++) {
                int r = colb + j;   // output head-dim
                rb[j] = *(const u64*)&Vt[r * 64 + (k0 ^ ((r & 7) << 3))];
            }
            #pragma unroll
            for (int i = 0; i < 4; i++)
                #pragma unroll
                for (int j = 0; j < 4; j++) fma2(accO[i][j], ra[i], rb[j]);
        }
    }

    // epilogue
    #pragma unroll
    for (int i = 0; i < 4; i++) {
        float inv = 1.0f / lrow[i];
        int q = q0 + ty * 4 + i;
        float2 p0 = unpack2(accO[i][0]);
        float2 p1 = unpack2(accO[i][1]);
        float2 p2 = unpack2(accO[i][2]);
        float2 p3 = unpack2(accO[i][3]);
        float4 o = make_float4((p0.x + p0.y) * inv, (p1.x + p1.y) * inv,
                               (p2.x + p2.y) * inv, (p3.x + p3.y) * inv);
        *(float4*)&out[(size_t)q * D_Q + h * HEAD_DIM + tx * 4] = o;
    }
}

// ---------------------------------------------------------------------------
// Launch. inputs: 0:x 1:sin 2:cos 3:mask 4:Wq 5:Wk 6:Wv 7:Wo 8:bo 9:q_scale 10:k_scale
// ---------------------------------------------------------------------------
extern "C" void kernel_launch(void* const* d_in, const int* in_sizes, int n_in,
                              void* d_out, int out_size)
{
    const float* x       = (const float*)d_in[0];
    const float* sinp    = (const float*)d_in[1];
    const float* cosp    = (const float*)d_in[2];
    const float* Wq      = (const float*)d_in[4];
    const float* Wk      = (const float*)d_in[5];
    const float* Wv      = (const float*)d_in[6];
    const float* Wo      = (const float*)d_in[7];
    const float* bo      = (const float*)d_in[8];
    const float* q_scale = (const float*)d_in[9];
    const float* k_scale = (const float*)d_in[10];
    float* out = (float*)d_out;

    float *pw, *pqkv, *pao;
    cudaGetSymbolAddress((void**)&pw, g_w);
    cudaGetSymbolAddress((void**)&pqkv, g_qkv);
    cudaGetSymbolAddress((void**)&pao, g_ao);

    cudaFuncSetAttribute(attn_flash, cudaFuncAttributeMaxDynamicSharedMemorySize, ATTN_SMEM);

    // 1. Concatenate weights, one fused QKV GEMM
    concat_w_kernel<<<(D_MODEL * D_QKV / 4) / 256, 256>>>(Wq, Wk, Wv, pw);
    sgemm128<<<dim3(D_QKV / 128, S_LEN / 128), 256>>>(x, pw, pqkv, nullptr, S_LEN, D_QKV, D_MODEL);

    // 2. RMSNorm + RoPE in place (q: 32 heads, k: 8 heads)
    norm_rope4<<<dim3(S_LEN, HEADS / 4), 256>>>(pqkv,       q_scale, sinp, cosp);
    norm_rope4<<<dim3(S_LEN, NKV   / 4), 256>>>(pqkv + D_Q, k_scale, sinp, cosp);

    // 3. Flash attention
    attn_flash<<<dim3(S_LEN / 64, HEADS), 256, ATTN_SMEM>>>(pqkv, pao);

    // 4. Output projection + bias
    sgemm128<<<dim3(D_MODEL / 128, S_LEN / 128), 256>>>(pao, Wo, out, bo, S_LEN, D_MODEL, D_Q);
}